// round 17
// baseline (speedup 1.0000x reference)
#include <cuda_runtime.h>
#include <math_constants.h>

// MaxPlusDense: out[b,u] = max( max_i (x[b,i] - kernel[i,u]), bias[u] )
// B=256, D=1024, U=1024, fp32.
//
// R16 core (proven plateau kernel) + split-K=2 for 2 CTAs/SM -> 4 warps/SMSP.
// Same inner loop, same staging, bias folded into accumulator init.
// Tail: replay-safe last-CTA-per-tile max-reduction via atom.acq_rel
// (no __threadfence -> no CCTL.IVALL).

#define B_DIM 256
#define D_DIM 1024
#define U_DIM 1024

#define SPLITS 2
#define KSEG   (D_DIM / SPLITS)   // 512
#define BM 32
#define BN 64
#define BK 32
#define NT 256
#define NTILE (KSEG / BK)         // 16
#define NTILES ((B_DIM / BM) * (U_DIM / BN))   // 128

#define XPITCH (BM + 2)           // 34
#define WPITCH (BN + 4)           // 68 (float4-aligned rows)

__device__ float    g_scratch[SPLITS][B_DIM * U_DIM];   // 2 MB partials
__device__ unsigned g_cnt[NTILES];                      // monotonic counters

__device__ __forceinline__ unsigned atom_add_acqrel(unsigned* p, unsigned v) {
    unsigned old;
    asm volatile("atom.acq_rel.gpu.global.add.u32 %0, [%1], %2;"
                 : "=r"(old) : "l"(p), "r"(v) : "memory");
    return old;
}

__global__ __launch_bounds__(NT, 2) void maxplus_fused(
    const float* __restrict__ X,     // (B, D)
    const float* __restrict__ W,     // (D, U)
    const float* __restrict__ bias,  // (U,)
    float* __restrict__ out)         // (B, U)
{
    __shared__ float xs[2][BK][XPITCH];   // x^T tiles: xs[buf][k][m]
    __shared__ float ws[2][BK][WPITCH];   // W tiles:   ws[buf][k][n]
    __shared__ int s_last;

    const int tid   = threadIdx.x;
    const int bn    = blockIdx.x * BN;
    const int bm    = blockIdx.y * BM;
    const int split = blockIdx.z;
    const int kbase = split * KSEG;

    // microtile: 2 rows (m) x 4 cols (n)  [R16 fragment maps]
    const int tm = (tid & 15) * 2;     // 0..30
    const int tn = (tid >> 4) * 4;     // 0..60

    // staging maps (R16-proven)
    const int xr = tid >> 3;           // 0..31 : m
    const int xc = (tid & 7) * 4;      // 0..28 : k quad
    const int wr = tid >> 4;           // 0..15 : k row (+16)
    const int wc = (tid & 15) * 4;     // 0..60 : n quad

    const float* xg = X + (size_t)(bm + xr) * D_DIM + kbase + xc;
    const float* wg = W + (size_t)(kbase + wr) * U_DIM + bn + wc;

    // bias-initialized accumulators (max is monotone: correct in both splits)
    const float4 bv = *(const float4*)&bias[bn + tn];
    float4 q0 = bv, q1 = bv;

    // prologue: stage tile 0 in registers
    float4 xv, wv0, wv1;
    xv  = *(const float4*)(xg);
    wv0 = *(const float4*)(wg);
    wv1 = *(const float4*)(wg + (size_t)16 * U_DIM);

#pragma unroll 1
    for (int t = 0; t < NTILE; t++) {
        const int cur = t & 1;

        // ---- commit staged regs to smem buffer `cur` ----
        xs[cur][xc + 0][xr] = xv.x;
        xs[cur][xc + 1][xr] = xv.y;
        xs[cur][xc + 2][xr] = xv.z;
        xs[cur][xc + 3][xr] = xv.w;
        *(float4*)&ws[cur][wr     ][wc] = wv0;
        *(float4*)&ws[cur][wr + 16][wc] = wv1;
        __syncthreads();   // one barrier per tile

        // ---- prefetch tile t+1 (L2-resident); hidden by 32-k compute ----
        if (t + 1 < NTILE) {
            const int kb = (t + 1) * BK;
            xv  = *(const float4*)(xg + kb);
            wv0 = *(const float4*)(wg + (size_t)kb * U_DIM);
            wv1 = *(const float4*)(wg + (size_t)(kb + 16) * U_DIM);
        }

        // ---- compute 32 k-steps from buffer `cur` ----
#pragma unroll
        for (int kk = 0; kk < BK; kk++) {
            const float2 a = *(const float2*)&xs[cur][kk][tm];
            const float4 b = *(const float4*)&ws[cur][kk][tn];
            q0.x = fmaxf(q0.x, a.x - b.x);
            q0.y = fmaxf(q0.y, a.x - b.y);
            q0.z = fmaxf(q0.z, a.x - b.z);
            q0.w = fmaxf(q0.w, a.x - b.w);
            q1.x = fmaxf(q1.x, a.y - b.x);
            q1.y = fmaxf(q1.y, a.y - b.y);
            q1.z = fmaxf(q1.z, a.y - b.z);
            q1.w = fmaxf(q1.w, a.y - b.w);
        }
        // next iteration's STS targets the other buffer; its barrier orders reuse
    }

    // ---- write split partials ----
    {
        float* dst = g_scratch[split];
        *(float4*)&dst[(size_t)(bm + tm    ) * U_DIM + bn + tn] = q0;
        *(float4*)&dst[(size_t)(bm + tm + 1) * U_DIM + bn + tn] = q1;
    }
    __syncthreads();   // partial STGs happen-before tid0's release-atom

    // ---- last-arriving split reduces this tile ----
    if (tid == 0) {
        unsigned old = atom_add_acqrel(&g_cnt[blockIdx.y * (U_DIM / BN) + blockIdx.x], 1u);
        s_last = (((old + 1) & (SPLITS - 1)) == 0) ? 1 : 0;
    }
    __syncthreads();   // tid0's acquire happens-before all threads' reads

    if (s_last) {
#pragma unroll
        for (int i = 0; i < 2; i++) {
            const size_t off = (size_t)(bm + tm + i) * U_DIM + bn + tn;
            const float4 p0 = __ldcg((const float4*)&g_scratch[0][off]);
            const float4 p1 = __ldcg((const float4*)&g_scratch[1][off]);
            float4 o;
            o.x = fmaxf(p0.x, p1.x);
            o.y = fmaxf(p0.y, p1.y);
            o.z = fmaxf(p0.z, p1.z);
            o.w = fmaxf(p0.w, p1.w);
            *(float4*)&out[off] = o;
        }
    }
}

extern "C" void kernel_launch(void* const* d_in, const int* in_sizes, int n_in,
                              void* d_out, int out_size)
{
    const float* x      = (const float*)d_in[0];   // (256, 1024)
    const float* kernel = (const float*)d_in[1];   // (1024, 1024)
    const float* bias   = (const float*)d_in[2];   // (1024,)
    float* out          = (float*)d_out;           // (256, 1024)

    dim3 grid(U_DIM / BN, B_DIM / BM, SPLITS);     // (16, 8, 2) = 256 CTAs
    maxplus_fused<<<grid, NT>>>(x, kernel, bias, out);
}